// round 2
// baseline (speedup 1.0000x reference)
#include <cuda_runtime.h>
#include <math.h>

#define Bsz 128
#define Tt  512
#define H3  1536
#define BT  65536
#define NCTA 128

__device__ float g_G[201326592];   // [dir][b*T+t][1536]
__device__ float g_out[67108864];  // [b][t][1024]
__device__ float g_h[262144];      // [phase][dir][b][512]
__device__ float g_scores[65536];
__device__ int   g_tok2[131072];
__device__ unsigned g_cnt, g_gen, g_done;

// ---------------------------------------------------------------- K0
__global__ void k_init(const int* __restrict__ tokens, const int* __restrict__ lengths)
{
    int i = blockIdx.x * blockDim.x + threadIdx.x;
    if (i >= BT) return;
    int b = i >> 9, t = i & 511;
    g_tok2[i] = tokens[i];
    int rt = lengths[b] - 1 - t;
    if (rt < 0) rt = 0;
    g_tok2[BT + i] = tokens[(b << 9) + rt];
    g_scores[i] = 0.f;
}

// ---------------------------------------------------------------- K1: G = emb[tok] @ Wih^T + bih
__global__ void __launch_bounds__(256) k_gemm_ih(
    const float* __restrict__ emb,
    const float* __restrict__ Wf, const float* __restrict__ bf,
    const float* __restrict__ Wb, const float* __restrict__ bb)
{
    const int d = blockIdx.z;
    const float* W    = d ? Wb : Wf;
    const float* bias = d ? bb : bf;
    __shared__ float As[8][128], Bs[8][128];
    __shared__ int toks[128];
    int tid = threadIdx.x;
    int mb = blockIdx.x * 128, nb = blockIdx.y * 128;
    if (tid < 128) toks[tid] = g_tok2[d * BT + mb + tid];
    __syncthreads();
    int lm = tid >> 1, lk = (tid & 1) * 4;
    const float* Arow = emb + (long)toks[lm] * 512;
    const float* Brow = W   + (long)(nb + lm) * 512;
    int tx = tid & 15, ty = tid >> 4;
    int m0 = ty * 8, n0 = tx * 8;
    float acc[8][8];
    #pragma unroll
    for (int i = 0; i < 8; i++)
        #pragma unroll
        for (int j = 0; j < 8; j++) acc[i][j] = 0.f;

    for (int kt = 0; kt < 512; kt += 8) {
        float4 a = *(const float4*)(Arow + kt + lk);
        float4 w = *(const float4*)(Brow + kt + lk);
        As[lk+0][lm]=a.x; As[lk+1][lm]=a.y; As[lk+2][lm]=a.z; As[lk+3][lm]=a.w;
        Bs[lk+0][lm]=w.x; Bs[lk+1][lm]=w.y; Bs[lk+2][lm]=w.z; Bs[lk+3][lm]=w.w;
        __syncthreads();
        #pragma unroll
        for (int k = 0; k < 8; k++) {
            float av[8], wv[8];
            *(float4*)av     = *(float4*)&As[k][m0];
            *(float4*)(av+4) = *(float4*)&As[k][m0+4];
            *(float4*)wv     = *(float4*)&Bs[k][n0];
            *(float4*)(wv+4) = *(float4*)&Bs[k][n0+4];
            #pragma unroll
            for (int i = 0; i < 8; i++)
                #pragma unroll
                for (int j = 0; j < 8; j++)
                    acc[i][j] = fmaf(av[i], wv[j], acc[i][j]);
        }
        __syncthreads();
    }
    float* Cb = g_G + (long)d * BT * H3;
    #pragma unroll
    for (int i = 0; i < 8; i++) {
        float* cp = Cb + (long)(mb + m0 + i) * H3 + nb + n0;
        #pragma unroll
        for (int j = 0; j < 8; j++) cp[j] = acc[i][j] + bias[nb + n0 + j];
    }
}

// ---------------------------------------------------------------- grid barrier (monotonic)
__device__ __forceinline__ void grid_barrier(unsigned target)
{
    __syncthreads();
    if (threadIdx.x == 0) {
        __threadfence();
        unsigned a = atomicAdd(&g_cnt, 1u) + 1u;
        if (a == target * NCTA) {
            atomicAdd(&g_gen, 1u);
        } else {
            while (*(volatile unsigned*)&g_gen < target) { }
        }
        __threadfence();
    }
    __syncthreads();
}

// ---------------------------------------------------------------- K2: persistent bi-GRU recurrence
extern __shared__ float smem_gru[];
__global__ void __launch_bounds__(256) k_gru(
    const float* __restrict__ Whh_f, const float* __restrict__ bhh_f,
    const float* __restrict__ Whh_b, const float* __restrict__ bhh_b,
    const int*   __restrict__ lengths)
{
    float* Ws  = smem_gru;            // [512][96] transposed Whh slice
    float* hsm = smem_gru + 512 * 96; // [32][72]  h chunk (b-major)
    int tid = threadIdx.x;
    int cid = blockIdx.x;
    int d  = cid >> 6;
    int r  = cid & 63;
    int kg = r & 15;       // unit group (32 hidden units)
    int bg = r >> 4;       // batch group (32 rows)
    const float* Whh = d ? Whh_b : Whh_f;
    const float* bhh = d ? bhh_b : bhh_f;
    int tx = tid & 31, ty = tid >> 5;
    int u  = kg * 32 + tx;
    int b0 = bg * 32 + ty * 4;

    // cache the CTA's 96 Whh rows (gates r,z,n for its 32 units), transposed
    for (int idx = tid; idx < 96 * 128; idx += 256) {
        int row = idx >> 7;            // local j = g*32 + jl
        int g = row >> 5, jl = row & 31;
        int k4 = (idx & 127) << 2;
        float4 w = *(const float4*)(Whh + (long)(g * 512 + kg * 32 + jl) * 512 + k4);
        Ws[(k4+0)*96 + row] = w.x;
        Ws[(k4+1)*96 + row] = w.y;
        Ws[(k4+2)*96 + row] = w.z;
        Ws[(k4+3)*96 + row] = w.w;
    }
    float bh0 = bhh[u], bh1 = bhh[512 + u], bh2 = bhh[1024 + u];
    int len[4];
    #pragma unroll
    for (int i = 0; i < 4; i++) len[i] = lengths[b0 + i];

    // zero h phase 0 for this CTA's (b,u) slice
    for (int i = tid; i < 1024; i += 256) {
        int bb = bg * 32 + (i >> 5);
        int uu = kg * 32 + (i & 31);
        g_h[((0 * 2 + d) * 128 + bb) * 512 + uu] = 0.f;
    }
    grid_barrier(1);

    for (int t = 0; t < 512; ++t) {
        int p = t & 1;
        const float* hbase = g_h + (p * 2 + d) * 128 * 512;
        float ir[4], iz[4], inn[4];
        #pragma unroll
        for (int i = 0; i < 4; i++) {
            const float* gp = g_G + (long)d * BT * H3 + ((long)(b0 + i) * 512 + t) * H3;
            ir[i]  = __ldg(gp + u);
            iz[i]  = __ldg(gp + 512 + u);
            inn[i] = __ldg(gp + 1024 + u);
        }
        float a0[4] = {0,0,0,0}, a1[4] = {0,0,0,0}, a2[4] = {0,0,0,0};

        for (int kc = 0; kc < 512; kc += 64) {
            __syncthreads();
            {   // stage h chunk: 32 b x 64 k, via L2 (ldcg)
                int bl = tid >> 3;
                int kk = (tid & 7) << 3;
                const float* hp = hbase + (bg * 32 + bl) * 512 + kc + kk;
                float4 h0 = __ldcg((const float4*)hp);
                float4 h1 = __ldcg((const float4*)(hp + 4));
                float* dst = hsm + bl * 72 + kk;
                *(float4*)dst       = h0;
                *(float4*)(dst + 4) = h1;
            }
            __syncthreads();
            #pragma unroll 16
            for (int k = 0; k < 64; k++) {
                const float* wp = Ws + (kc + k) * 96;
                float w0 = wp[tx], w1 = wp[32 + tx], w2 = wp[64 + tx];
                #pragma unroll
                for (int i = 0; i < 4; i++) {
                    float hv = hsm[(ty * 4 + i) * 72 + k];
                    a0[i] = fmaf(hv, w0, a0[i]);
                    a1[i] = fmaf(hv, w1, a1[i]);
                    a2[i] = fmaf(hv, w2, a2[i]);
                }
            }
        }
        float* hw = g_h + ((p ^ 1) * 2 + d) * 128 * 512;
        #pragma unroll
        for (int i = 0; i < 4; i++) {
            int bb = b0 + i;
            float hprev = __ldcg(hbase + bb * 512 + u);
            float rr = 1.f / (1.f + expf(-(ir[i]  + a0[i] + bh0)));
            float zz = 1.f / (1.f + expf(-(iz[i]  + a1[i] + bh1)));
            float nn = tanhf(inn[i] + rr * (a2[i] + bh2));
            float hn = (1.f - zz) * nn + zz * hprev;
            bool m = (t < len[i]);
            hw[bb * 512 + u] = m ? hn : hprev;
            float* ob = g_out + (long)bb * 512 * 1024;
            if (d == 0) {
                ob[(long)t * 1024 + u] = m ? hn : 0.f;
            } else {
                int row = m ? (len[i] - 1 - t) : t;
                ob[(long)row * 1024 + 512 + u] = m ? hn : 0.f;
            }
        }
        grid_barrier((unsigned)(t + 2));
    }
    __syncthreads();
    if (tid == 0) {
        unsigned old = atomicAdd(&g_done, 1u);
        if (old == NCTA - 1) { g_cnt = 0; g_gen = 0; g_done = 0; __threadfence(); }
    }
}

// ---------------------------------------------------------------- K3: scores += tanh(out@Wp^T+bp) . ctx
__global__ void __launch_bounds__(256) k_gemm_proj(
    const float* __restrict__ Wp, const float* __restrict__ bp,
    const float* __restrict__ ctx)
{
    __shared__ float As[8][128], Bs[8][128];
    int tid = threadIdx.x;
    int mb = blockIdx.x * 128, nb = blockIdx.y * 128;
    int lm = tid >> 1, lk = (tid & 1) * 4;
    const float* Arow = g_out + (long)(mb + lm) * 1024;
    const float* Brow = Wp    + (long)(nb + lm) * 1024;
    int tx = tid & 15, ty = tid >> 4;
    int m0 = ty * 8, n0 = tx * 8;
    float acc[8][8];
    #pragma unroll
    for (int i = 0; i < 8; i++)
        #pragma unroll
        for (int j = 0; j < 8; j++) acc[i][j] = 0.f;

    for (int kt = 0; kt < 1024; kt += 8) {
        float4 a = *(const float4*)(Arow + kt + lk);
        float4 w = *(const float4*)(Brow + kt + lk);
        As[lk+0][lm]=a.x; As[lk+1][lm]=a.y; As[lk+2][lm]=a.z; As[lk+3][lm]=a.w;
        Bs[lk+0][lm]=w.x; Bs[lk+1][lm]=w.y; Bs[lk+2][lm]=w.z; Bs[lk+3][lm]=w.w;
        __syncthreads();
        #pragma unroll
        for (int k = 0; k < 8; k++) {
            float av[8], wv[8];
            *(float4*)av     = *(float4*)&As[k][m0];
            *(float4*)(av+4) = *(float4*)&As[k][m0+4];
            *(float4*)wv     = *(float4*)&Bs[k][n0];
            *(float4*)(wv+4) = *(float4*)&Bs[k][n0+4];
            #pragma unroll
            for (int i = 0; i < 8; i++)
                #pragma unroll
                for (int j = 0; j < 8; j++)
                    acc[i][j] = fmaf(av[i], wv[j], acc[i][j]);
        }
        __syncthreads();
    }
    #pragma unroll
    for (int i = 0; i < 8; i++) {
        float part = 0.f;
        #pragma unroll
        for (int j = 0; j < 8; j++) {
            float v = tanhf(acc[i][j] + bp[nb + n0 + j]);
            part = fmaf(v, ctx[nb + n0 + j], part);
        }
        #pragma unroll
        for (int o = 8; o > 0; o >>= 1)
            part += __shfl_xor_sync(0xffffffffu, part, o);
        if (tx == 0) atomicAdd(&g_scores[mb + m0 + i], part);
    }
}

// ---------------------------------------------------------------- K4: softmax + pooling + SELU + logits
__global__ void __launch_bounds__(512) k_final(
    const int* __restrict__ lengths,
    const float* __restrict__ Wl, const float* __restrict__ bl,
    float* __restrict__ out, int out_size)
{
    __shared__ float sh[512];
    __shared__ float attn[512];
    __shared__ float lg[2];
    int b = blockIdx.x, tid = threadIdx.x;
    int len = lengths[b];
    float s = (tid < len) ? g_scores[b * 512 + tid] : -1e30f;
    sh[tid] = s; __syncthreads();
    for (int o = 256; o > 0; o >>= 1) { if (tid < o) sh[tid] = fmaxf(sh[tid], sh[tid + o]); __syncthreads(); }
    float mx = sh[0]; __syncthreads();
    float e = (tid < len) ? expf(s - mx) : 0.f;
    sh[tid] = e; __syncthreads();
    for (int o = 256; o > 0; o >>= 1) { if (tid < o) sh[tid] += sh[tid + o]; __syncthreads(); }
    float a = e / sh[0];
    attn[tid] = a;
    int attn_ofs = (out_size >= 65792) ? 256 : 0;
    if (out_size != 256) out[attn_ofs + b * 512 + tid] = a;
    if (tid == 0) { lg[0] = 0.f; lg[1] = 0.f; }
    __syncthreads();

    const float* ob = g_out + (long)b * 512 * 1024;
    float s0 = 0.f, s1 = 0.f;
    for (int t = 0; t < 512; t++) {
        float at = attn[t];
        s0 = fmaf(at, ob[(long)t * 1024 + tid],       s0);
        s1 = fmaf(at, ob[(long)t * 1024 + 512 + tid], s1);
    }
    const float SC = 1.0507009873554805f, AL = 1.6732632423543772f;
    s0 = (s0 > 0.f) ? SC * s0 : SC * AL * (expf(s0) - 1.f);
    s1 = (s1 > 0.f) ? SC * s1 : SC * AL * (expf(s1) - 1.f);
    float p0 = s0 * Wl[tid]        + s1 * Wl[512 + tid];
    float p1 = s0 * Wl[1024 + tid] + s1 * Wl[1536 + tid];
    #pragma unroll
    for (int o = 16; o > 0; o >>= 1) {
        p0 += __shfl_xor_sync(0xffffffffu, p0, o);
        p1 += __shfl_xor_sync(0xffffffffu, p1, o);
    }
    if ((tid & 31) == 0) { atomicAdd(&lg[0], p0); atomicAdd(&lg[1], p1); }
    __syncthreads();
    if (tid < 2 && out_size != 65536) out[b * 2 + tid] = lg[tid] + bl[tid];
}

// ---------------------------------------------------------------- launch
extern "C" void kernel_launch(void* const* d_in, const int* in_sizes, int n_in,
                              void* d_out, int out_size)
{
    const int*   tokens  = (const int*)d_in[0];
    const int*   lengths = (const int*)d_in[1];
    const float* emb     = (const float*)d_in[2];
    const float* Wih_f   = (const float*)d_in[3];
    const float* Whh_f   = (const float*)d_in[4];
    const float* bih_f   = (const float*)d_in[5];
    const float* bhh_f   = (const float*)d_in[6];
    const float* Wih_b   = (const float*)d_in[7];
    const float* Whh_b   = (const float*)d_in[8];
    const float* bih_b   = (const float*)d_in[9];
    const float* bhh_b   = (const float*)d_in[10];
    const float* Wp      = (const float*)d_in[11];
    const float* bp      = (const float*)d_in[12];
    const float* ctx     = (const float*)d_in[13];
    const float* Wl      = (const float*)d_in[14];
    const float* bl      = (const float*)d_in[15];
    float* out = (float*)d_out;

    k_init<<<BT / 256, 256>>>(tokens, lengths);

    dim3 g1(512, 12, 2);
    k_gemm_ih<<<g1, 256>>>(emb, Wih_f, bih_f, Wih_b, bih_b);

    int smem_bytes = (512 * 96 + 32 * 72) * 4;
    cudaFuncSetAttribute(k_gru, cudaFuncAttributeMaxDynamicSharedMemorySize, smem_bytes);
    k_gru<<<NCTA, 256, smem_bytes>>>(Whh_f, bhh_f, Whh_b, bhh_b, lengths);

    dim3 g3(512, 4);
    k_gemm_proj<<<g3, 256>>>(Wp, bp, ctx);

    k_final<<<Bsz, 512>>>(lengths, Wl, bl, out, out_size);
}